// round 15
// baseline (speedup 1.0000x reference)
#include <cuda_runtime.h>

namespace {
constexpr int NB       = 16;
constexpr int Lp       = 196;
constexpr int Dd       = 1024;
constexpr int PPIX     = 768;
constexpr int NBINS    = 64;
constexpr int LEN_KEEP = 49;
constexpr int NPATCH   = NB * Lp;            // 3136
constexpr int TOTAL_PIX = NPATCH * PPIX;
constexpr int MM_BLOCKS = 1184;              // 8 blocks/SM — MLP for the min/max scan
}

__device__ uint2  g_mm[MM_BLOCKS];
__device__ float2 g_mmf;                      // folded (vmin, vmax)
__device__ float  g_ent0[NPATCH];

__device__ __forceinline__ unsigned fenc(float f) {
    unsigned b = __float_as_uint(f);
    return (b & 0x80000000u) ? ~b : (b | 0x80000000u);
}
__device__ __forceinline__ float fdec(unsigned u) {
    return (u & 0x80000000u) ? __uint_as_float(u & 0x7FFFFFFFu)
                             : __uint_as_float(~u);
}

__device__ __forceinline__ float exp_acc(float x) {
#ifndef __FAST_MATH__
    return expf(x);
#else
    float j = __fmaf_rn(x, 1.4426950408889634f, 12582912.0f);
    float n = __fadd_rn(j, -12582912.0f);
    float r = __fmaf_rn(n, -0.693359375f, x);
    r = __fmaf_rn(n, 2.12194440e-4f, r);
    float p = 1.3888889e-3f;
    p = __fmaf_rn(p, r, 8.3333333e-3f);
    p = __fmaf_rn(p, r, 4.1666668e-2f);
    p = __fmaf_rn(p, r, 1.6666667e-1f);
    p = __fmaf_rn(p, r, 0.5f);
    p = __fmaf_rn(p, r, 1.0f);
    p = __fmaf_rn(p, r, 1.0f);
    int ni = (int)n;
    float sc = __int_as_float((ni + 127) << 23);
    return p * sc;
#endif
}
__device__ __forceinline__ float log_acc(float x) {
#ifndef __FAST_MATH__
    return logf(x);
#else
    int ei = (int)(__float_as_uint(x) >> 23) - 127;
    float m = __uint_as_float((__float_as_uint(x) & 0x007FFFFFu) | 0x3F800000u);
    if (m > 1.41421356f) { m *= 0.5f; ei += 1; }
    float f = m - 1.0f;
    float u = f / (2.0f + f);
    float u2 = u * u;
    float pp = 0.0944026f;
    pp = __fmaf_rn(pp, u2, 0.132909f);
    pp = __fmaf_rn(pp, u2, 0.199887f);
    pp = __fmaf_rn(pp, u2, 0.4f);
    pp = __fmaf_rn(pp, u2, 0.666666687f);
    pp = __fmaf_rn(pp, u2, 2.0f);
    float r = pp * u;
    return __fmaf_rn((float)ei, 0.693147182f, r);
#endif
}

__device__ __forceinline__ float bin_value(int b) {
    return (b == NBINS - 1) ? 1.0f : __fmul_rn((float)b, 1.0f / 63.0f);
}

__global__ void minmax_kernel(const float* __restrict__ img) {
    __shared__ unsigned smin[8], smax[8];
    unsigned lmin = 0xFFFFFFFFu, lmax = 0u;
    const int n4 = TOTAL_PIX / 4;
    const float4* p4 = (const float4*)img;
    for (int i = blockIdx.x * blockDim.x + threadIdx.x; i < n4;
         i += blockDim.x * gridDim.x) {
        float4 v = p4[i];
        unsigned e;
        e = fenc(v.x); lmin = min(lmin, e); lmax = max(lmax, e);
        e = fenc(v.y); lmin = min(lmin, e); lmax = max(lmax, e);
        e = fenc(v.z); lmin = min(lmin, e); lmax = max(lmax, e);
        e = fenc(v.w); lmin = min(lmin, e); lmax = max(lmax, e);
    }
#pragma unroll
    for (int o = 16; o; o >>= 1) {
        lmin = min(lmin, __shfl_xor_sync(0xffffffffu, lmin, o));
        lmax = max(lmax, __shfl_xor_sync(0xffffffffu, lmax, o));
    }
    const int w = threadIdx.x >> 5;
    if ((threadIdx.x & 31) == 0) { smin[w] = lmin; smax[w] = lmax; }
    __syncthreads();
    if (threadIdx.x == 0) {
        lmin = smin[0]; lmax = smax[0];
#pragma unroll
        for (int j = 1; j < 8; j++) { lmin = min(lmin, smin[j]); lmax = max(lmax, smax[j]); }
        g_mm[blockIdx.x] = make_uint2(lmin, lmax);
    }
}

// fold 1184 partials into one float2 (1 block of 256)
__global__ void mm_reduce_kernel() {
    __shared__ unsigned smin[8], smax[8];
    const int tid = threadIdx.x;
    unsigned lmin = 0xFFFFFFFFu, lmax = 0u;
    for (int i = tid; i < MM_BLOCKS; i += 256) {
        uint2 v = g_mm[i];
        lmin = min(lmin, v.x); lmax = max(lmax, v.y);
    }
#pragma unroll
    for (int o = 16; o; o >>= 1) {
        lmin = min(lmin, __shfl_xor_sync(0xffffffffu, lmin, o));
        lmax = max(lmax, __shfl_xor_sync(0xffffffffu, lmax, o));
    }
    const int w = tid >> 5;
    if ((tid & 31) == 0) { smin[w] = lmin; smax[w] = lmax; }
    __syncthreads();
    if (tid == 0) {
        lmin = smin[0]; lmax = smax[0];
#pragma unroll
        for (int j = 1; j < 8; j++) { lmin = min(lmin, smin[j]); lmax = max(lmax, smax[j]); }
        g_mmf = make_float2(fdec(lmin), fdec(lmax));
    }
}

// Hypothesis-0 entropy (m0 mean-order + sum64 variant 0), bit-exact — chain
// orders verbatim from R13/R14. Phase C batched (identical fadd sequence,
// overlapped loads, fewer branches).
__global__ __launch_bounds__(256) void entropy_kernel(const float* __restrict__ img) {
    __shared__ float s_nv[PPIX];
    __shared__ float s_tv[8][PPIX];   // interleaved: class-j entry i at [w][i*8+j]
    __shared__ float s_pdf[NBINS];
    __shared__ float s_e8[8][8];
    __shared__ float s_tmp[NBINS];

    const int p   = blockIdx.x;
    const int tid = threadIdx.x;
    const int w   = tid >> 5;
    const int l   = tid & 31;
    const int cls = l & 7;

    const float2 mm   = g_mmf;
    const float vmin  = mm.x;
    const float range = __fadd_rn(mm.y, -vmin);

    const float* base = img + (size_t)p * PPIX;
    for (int i = tid; i < PPIX; i += 256)
        s_nv[i] = __fdiv_rn(__fadd_rn(base[i], -vmin), range);
    __syncthreads();

    float* tv = s_tv[w];
    const unsigned ltmask = (1u << l) - 1u;
    const unsigned cm = 0x01010101u << cls;   // lanes of my residue class

    for (int bin = w; bin < NBINS; bin += 8) {
        const float binv = bin_value(bin);
        const float fb   = (float)bin;

        // Phase A: per-class compaction of in-window nv values (ascending v)
        int cntc = 0;
#pragma unroll
        for (int k = 0; k < 24; k++) {
            const float nvv = s_nv[l + 32 * k];
            const bool iw = fabsf(__fmaf_rn(nvv, 63.0f, -fb)) <= 6.0f;
            const unsigned m  = __ballot_sync(0xffffffffu, iw);
            const unsigned mc = m & cm;
            if (iw) tv[(cntc + __popc(mc & ltmask)) * 8 + cls] = nvv;
            cntc += __popc(mc);
        }
        __syncwarp();

        // Phase B: dense terms in place (identical term values)
        for (int i = (l >> 3); i < cntc; i += 4) {
            const int s = i * 8 + cls;
            const float nvv = tv[s];
            const float res = __fadd_rn(nvv, -binv);
            const float z   = __fdiv_rn(res, 0.01f);
            tv[s] = exp_acc(__fmul_rn(-0.5f, __fmul_rn(z, z)));
        }
        __syncwarp();

        // Phase C: 8 stride-8 chains, in-order (identical fadd sequence);
        // batched x6: independent loads, then dependent fadds.
        if (l < 8) {
            float chain = 0.0f;
            int i = 0;
            for (; i + 6 <= cntc; i += 6) {
                const float a0 = tv[(i + 0) * 8 + l];
                const float a1 = tv[(i + 1) * 8 + l];
                const float a2 = tv[(i + 2) * 8 + l];
                const float a3 = tv[(i + 3) * 8 + l];
                const float a4 = tv[(i + 4) * 8 + l];
                const float a5 = tv[(i + 5) * 8 + l];
                chain = __fadd_rn(chain, a0);
                chain = __fadd_rn(chain, a1);
                chain = __fadd_rn(chain, a2);
                chain = __fadd_rn(chain, a3);
                chain = __fadd_rn(chain, a4);
                chain = __fadd_rn(chain, a5);
            }
            for (; i < cntc; i++)
                chain = __fadd_rn(chain, tv[i * 8 + l]);
            s_e8[w][l] = chain;
        }
        __syncwarp();

        if (l == 0) {
            const float* E8 = s_e8[w];
            float B[4];
#pragma unroll
            for (int j = 0; j < 4; j++) B[j] = __fadd_rn(E8[j], E8[j + 4]);
            const float m0 = __fadd_rn(__fadd_rn(B[0], B[1]), __fadd_rn(B[2], B[3]));
            s_pdf[bin] = __fdiv_rn(m0, 768.0f);
        }
        __syncwarp();
    }
    __syncthreads();

    // entropy over the 64 pdf values — sum64 variant 0, verbatim order
    if (w == 0) {
        if (l < 8) {
            float E = s_pdf[l];
#pragma unroll
            for (int k = 1; k < 8; k++) E = __fadd_rn(E, s_pdf[l + 8 * k]);
            s_e8[0][l] = E;
        }
        __syncwarp();
        float norm;
        if (l == 0) {
            const float* E = s_e8[0];
            float B[4];
#pragma unroll
            for (int j = 0; j < 4; j++) B[j] = __fadd_rn(E[j], E[j + 4]);
            norm = __fadd_rn(__fadd_rn(__fadd_rn(B[0], B[1]),
                                       __fadd_rn(B[2], B[3])), 1e-19f);
        }
        norm = __shfl_sync(0xffffffffu, norm, 0);

        {
            const float pa = __fadd_rn(__fdiv_rn(s_pdf[l], norm), 1e-19f);
            s_tmp[l] = __fmul_rn(pa, log_acc(pa));
            const float pb = __fadd_rn(__fdiv_rn(s_pdf[l + 32], norm), 1e-19f);
            s_tmp[l + 32] = __fmul_rn(pb, log_acc(pb));
        }
        __syncwarp();
        if (l < 8) {
            float E = s_tmp[l];
#pragma unroll
            for (int k = 1; k < 8; k++) E = __fadd_rn(E, s_tmp[l + 8 * k]);
            s_e8[0][l] = E;
        }
        __syncwarp();
        if (l == 0) {
            const float* E = s_e8[0];
            float B[4];
#pragma unroll
            for (int j = 0; j < 4; j++) B[j] = __fadd_rn(E[j], E[j + 4]);
            const float H = __fadd_rn(__fadd_rn(B[0], B[1]), __fadd_rn(B[2], B[3]));
            g_ent0[p] = -H;
        }
    }
}

// One block per batch: ballot ranks (identical predicate) + mask/ids_restore
// + keep-list + gather, all fused.
__global__ void rank_gather_kernel(const float* __restrict__ x,
                                   float* __restrict__ out) {
    __shared__ float s[Lp];
    __shared__ int   s_keep[LEN_KEEP];
    const int b = blockIdx.x, tid = threadIdx.x;
    const int w = tid >> 5, l = tid & 31;

    if (tid < Lp) s[tid] = g_ent0[b * Lp + tid];
    __syncthreads();

    float* outMask = out + (size_t)NB * LEN_KEEP * Dd;
    float* outRes  = outMask + (size_t)NB * Lp;

    for (int i = w; i < Lp; i += 8) {
        const float e = s[i];
        int cnt = 0;
        for (int j0 = 0; j0 < Lp; j0 += 32) {
            const int j = j0 + l;
            const bool pred = (j < Lp) && ((s[j] > e) || (s[j] == e && j < i));
            cnt += __popc(__ballot_sync(0xffffffffu, pred));
        }
        if (l == 0) {
            outRes[b * Lp + i]  = (float)cnt;
            outMask[b * Lp + i] = (cnt >= LEN_KEEP) ? 1.0f : 0.0f;
            if (cnt < LEN_KEEP) s_keep[cnt] = i;
        }
    }
    __syncthreads();

    const float4* xb = (const float4*)(x + (size_t)b * Lp * Dd);
    float4* ob = (float4*)(out + (size_t)b * LEN_KEEP * Dd);
#pragma unroll 7
    for (int r = 0; r < LEN_KEEP; r++) {
        const int src = s_keep[r];
        ob[r * (Dd / 4) + tid] = xb[src * (Dd / 4) + tid];
    }
}

extern "C" void kernel_launch(void* const* d_in, const int* in_sizes, int n_in,
                              void* d_out, int out_size) {
    (void)in_sizes; (void)n_in; (void)out_size;
    const float* x   = (const float*)d_in[0];   // (16,196,1024) fp32
    const float* img = (const float*)d_in[1];   // (16,196,768)  fp32
    float* out = (float*)d_out;                 // [x_masked | mask | ids_restore]

    minmax_kernel<<<MM_BLOCKS, 256>>>(img);
    mm_reduce_kernel<<<1, 256>>>();
    entropy_kernel<<<NPATCH, 256>>>(img);
    rank_gather_kernel<<<NB, 256>>>(x, out);
}

// round 16
// speedup vs baseline: 1.0028x; 1.0028x over previous
#include <cuda_runtime.h>

namespace {
constexpr int NB       = 16;
constexpr int Lp       = 196;
constexpr int Dd       = 1024;
constexpr int PPIX     = 768;
constexpr int NBINS    = 64;
constexpr int LEN_KEEP = 49;
constexpr int NPATCH   = NB * Lp;            // 3136
constexpr int TOTAL_PIX = NPATCH * PPIX;
constexpr int MM_BLOCKS = 1184;              // 8 blocks/SM — MLP for the min/max scan
}

__device__ uint2  g_mm[MM_BLOCKS];
__device__ float2 g_mmf;                      // folded (vmin, vmax)
__device__ float  g_ent0[NPATCH];
__device__ int    g_keep[NB * LEN_KEEP];

__device__ __forceinline__ unsigned fenc(float f) {
    unsigned b = __float_as_uint(f);
    return (b & 0x80000000u) ? ~b : (b | 0x80000000u);
}
__device__ __forceinline__ float fdec(unsigned u) {
    return (u & 0x80000000u) ? __uint_as_float(u & 0x7FFFFFFFu)
                             : __uint_as_float(~u);
}

__device__ __forceinline__ float exp_acc(float x) {
#ifndef __FAST_MATH__
    return expf(x);
#else
    float j = __fmaf_rn(x, 1.4426950408889634f, 12582912.0f);
    float n = __fadd_rn(j, -12582912.0f);
    float r = __fmaf_rn(n, -0.693359375f, x);
    r = __fmaf_rn(n, 2.12194440e-4f, r);
    float p = 1.3888889e-3f;
    p = __fmaf_rn(p, r, 8.3333333e-3f);
    p = __fmaf_rn(p, r, 4.1666668e-2f);
    p = __fmaf_rn(p, r, 1.6666667e-1f);
    p = __fmaf_rn(p, r, 0.5f);
    p = __fmaf_rn(p, r, 1.0f);
    p = __fmaf_rn(p, r, 1.0f);
    int ni = (int)n;
    float sc = __int_as_float((ni + 127) << 23);
    return p * sc;
#endif
}
__device__ __forceinline__ float log_acc(float x) {
#ifndef __FAST_MATH__
    return logf(x);
#else
    int ei = (int)(__float_as_uint(x) >> 23) - 127;
    float m = __uint_as_float((__float_as_uint(x) & 0x007FFFFFu) | 0x3F800000u);
    if (m > 1.41421356f) { m *= 0.5f; ei += 1; }
    float f = m - 1.0f;
    float u = f / (2.0f + f);
    float u2 = u * u;
    float pp = 0.0944026f;
    pp = __fmaf_rn(pp, u2, 0.132909f);
    pp = __fmaf_rn(pp, u2, 0.199887f);
    pp = __fmaf_rn(pp, u2, 0.4f);
    pp = __fmaf_rn(pp, u2, 0.666666687f);
    pp = __fmaf_rn(pp, u2, 2.0f);
    float r = pp * u;
    return __fmaf_rn((float)ei, 0.693147182f, r);
#endif
}

__device__ __forceinline__ float bin_value(int b) {
    return (b == NBINS - 1) ? 1.0f : __fmul_rn((float)b, 1.0f / 63.0f);
}

__global__ void minmax_kernel(const float* __restrict__ img) {
    __shared__ unsigned smin[8], smax[8];
    unsigned lmin = 0xFFFFFFFFu, lmax = 0u;
    const int n4 = TOTAL_PIX / 4;
    const float4* p4 = (const float4*)img;
    for (int i = blockIdx.x * blockDim.x + threadIdx.x; i < n4;
         i += blockDim.x * gridDim.x) {
        float4 v = p4[i];
        unsigned e;
        e = fenc(v.x); lmin = min(lmin, e); lmax = max(lmax, e);
        e = fenc(v.y); lmin = min(lmin, e); lmax = max(lmax, e);
        e = fenc(v.z); lmin = min(lmin, e); lmax = max(lmax, e);
        e = fenc(v.w); lmin = min(lmin, e); lmax = max(lmax, e);
    }
#pragma unroll
    for (int o = 16; o; o >>= 1) {
        lmin = min(lmin, __shfl_xor_sync(0xffffffffu, lmin, o));
        lmax = max(lmax, __shfl_xor_sync(0xffffffffu, lmax, o));
    }
    const int w = threadIdx.x >> 5;
    if ((threadIdx.x & 31) == 0) { smin[w] = lmin; smax[w] = lmax; }
    __syncthreads();
    if (threadIdx.x == 0) {
        lmin = smin[0]; lmax = smax[0];
#pragma unroll
        for (int j = 1; j < 8; j++) { lmin = min(lmin, smin[j]); lmax = max(lmax, smax[j]); }
        g_mm[blockIdx.x] = make_uint2(lmin, lmax);
    }
}

__global__ void mm_reduce_kernel() {
    __shared__ unsigned smin[8], smax[8];
    const int tid = threadIdx.x;
    unsigned lmin = 0xFFFFFFFFu, lmax = 0u;
    for (int i = tid; i < MM_BLOCKS; i += 256) {
        uint2 v = g_mm[i];
        lmin = min(lmin, v.x); lmax = max(lmax, v.y);
    }
#pragma unroll
    for (int o = 16; o; o >>= 1) {
        lmin = min(lmin, __shfl_xor_sync(0xffffffffu, lmin, o));
        lmax = max(lmax, __shfl_xor_sync(0xffffffffu, lmax, o));
    }
    const int w = tid >> 5;
    if ((tid & 31) == 0) { smin[w] = lmin; smax[w] = lmax; }
    __syncthreads();
    if (tid == 0) {
        lmin = smin[0]; lmax = smax[0];
#pragma unroll
        for (int j = 1; j < 8; j++) { lmin = min(lmin, smin[j]); lmax = max(lmax, smax[j]); }
        g_mmf = make_float2(fdec(lmin), fdec(lmax));
    }
}

// Hypothesis-0 entropy, bit-exact (chain orders verbatim). Phase A restructured:
// 3 chunks of 8 INDEPENDENT ballots (pipelined), then 8 ALU rounds consuming
// them — identical ballot values / slots / stored values.
__global__ __launch_bounds__(256) void entropy_kernel(const float* __restrict__ img) {
    __shared__ float s_nv[PPIX];
    __shared__ float s_tv[8][PPIX];   // interleaved: class-j entry i at [w][i*8+j]
    __shared__ float s_pdf[NBINS];
    __shared__ float s_e8[8][8];
    __shared__ float s_tmp[NBINS];

    const int p   = blockIdx.x;
    const int tid = threadIdx.x;
    const int w   = tid >> 5;
    const int l   = tid & 31;
    const int cls = l & 7;

    const float2 mm   = g_mmf;
    const float vmin  = mm.x;
    const float range = __fadd_rn(mm.y, -vmin);

    const float* base = img + (size_t)p * PPIX;
    for (int i = tid; i < PPIX; i += 256)
        s_nv[i] = __fdiv_rn(__fadd_rn(base[i], -vmin), range);
    __syncthreads();

    float* tv = s_tv[w];
    const unsigned ltmask = (1u << l) - 1u;
    const unsigned lbit   = 1u << l;
    const unsigned cm = 0x01010101u << cls;   // lanes of my residue class

    for (int bin = w; bin < NBINS; bin += 8) {
        const float binv = bin_value(bin);
        const float fb   = (float)bin;

        // Phase A (chunked): 8 independent ballots, then consume
        int cntc = 0;
#pragma unroll
        for (int kc = 0; kc < 3; kc++) {
            float    nv8[8];
            unsigned bal8[8];
#pragma unroll
            for (int j = 0; j < 8; j++) {
                nv8[j] = s_nv[l + 32 * (kc * 8 + j)];
                const bool iw = fabsf(__fmaf_rn(nv8[j], 63.0f, -fb)) <= 6.0f;
                bal8[j] = __ballot_sync(0xffffffffu, iw);
            }
#pragma unroll
            for (int j = 0; j < 8; j++) {
                const unsigned mc = bal8[j] & cm;
                if (bal8[j] & lbit)
                    tv[(cntc + __popc(mc & ltmask)) * 8 + cls] = nv8[j];
                cntc += __popc(mc);
            }
        }
        __syncwarp();

        // Phase B: dense terms in place (identical term values)
        for (int i = (l >> 3); i < cntc; i += 4) {
            const int s = i * 8 + cls;
            const float nvv = tv[s];
            const float res = __fadd_rn(nvv, -binv);
            const float z   = __fdiv_rn(res, 0.01f);
            tv[s] = exp_acc(__fmul_rn(-0.5f, __fmul_rn(z, z)));
        }
        __syncwarp();

        // Phase C: 8 stride-8 chains, in-order (identical fadd sequence)
        if (l < 8) {
            float chain = 0.0f;
            int i = 0;
            for (; i + 6 <= cntc; i += 6) {
                const float a0 = tv[(i + 0) * 8 + l];
                const float a1 = tv[(i + 1) * 8 + l];
                const float a2 = tv[(i + 2) * 8 + l];
                const float a3 = tv[(i + 3) * 8 + l];
                const float a4 = tv[(i + 4) * 8 + l];
                const float a5 = tv[(i + 5) * 8 + l];
                chain = __fadd_rn(chain, a0);
                chain = __fadd_rn(chain, a1);
                chain = __fadd_rn(chain, a2);
                chain = __fadd_rn(chain, a3);
                chain = __fadd_rn(chain, a4);
                chain = __fadd_rn(chain, a5);
            }
            for (; i < cntc; i++)
                chain = __fadd_rn(chain, tv[i * 8 + l]);
            s_e8[w][l] = chain;
        }
        __syncwarp();

        if (l == 0) {
            const float* E8 = s_e8[w];
            float B[4];
#pragma unroll
            for (int j = 0; j < 4; j++) B[j] = __fadd_rn(E8[j], E8[j + 4]);
            const float m0 = __fadd_rn(__fadd_rn(B[0], B[1]), __fadd_rn(B[2], B[3]));
            s_pdf[bin] = __fdiv_rn(m0, 768.0f);
        }
        __syncwarp();
    }
    __syncthreads();

    // entropy over the 64 pdf values — sum64 variant 0, verbatim order
    if (w == 0) {
        if (l < 8) {
            float E = s_pdf[l];
#pragma unroll
            for (int k = 1; k < 8; k++) E = __fadd_rn(E, s_pdf[l + 8 * k]);
            s_e8[0][l] = E;
        }
        __syncwarp();
        float norm;
        if (l == 0) {
            const float* E = s_e8[0];
            float B[4];
#pragma unroll
            for (int j = 0; j < 4; j++) B[j] = __fadd_rn(E[j], E[j + 4]);
            norm = __fadd_rn(__fadd_rn(__fadd_rn(B[0], B[1]),
                                       __fadd_rn(B[2], B[3])), 1e-19f);
        }
        norm = __shfl_sync(0xffffffffu, norm, 0);

        {
            const float pa = __fadd_rn(__fdiv_rn(s_pdf[l], norm), 1e-19f);
            s_tmp[l] = __fmul_rn(pa, log_acc(pa));
            const float pb = __fadd_rn(__fdiv_rn(s_pdf[l + 32], norm), 1e-19f);
            s_tmp[l + 32] = __fmul_rn(pb, log_acc(pb));
        }
        __syncwarp();
        if (l < 8) {
            float E = s_tmp[l];
#pragma unroll
            for (int k = 1; k < 8; k++) E = __fadd_rn(E, s_tmp[l + 8 * k]);
            s_e8[0][l] = E;
        }
        __syncwarp();
        if (l == 0) {
            const float* E = s_e8[0];
            float B[4];
#pragma unroll
            for (int j = 0; j < 4; j++) B[j] = __fadd_rn(E[j], E[j + 4]);
            const float H = __fadd_rn(__fadd_rn(B[0], B[1]), __fadd_rn(B[2], B[3]));
            g_ent0[p] = -H;
        }
    }
}

// One block per batch: ballot ranks (identical predicate), writes
// mask / ids_restore / keep-list. Gather is a separate wide kernel.
__global__ void rank_kernel(float* __restrict__ out) {
    __shared__ float s[Lp];
    const int b = blockIdx.x, tid = threadIdx.x;
    const int w = tid >> 5, l = tid & 31;

    if (tid < Lp) s[tid] = g_ent0[b * Lp + tid];
    __syncthreads();

    float* outMask = out + (size_t)NB * LEN_KEEP * Dd;
    float* outRes  = outMask + (size_t)NB * Lp;

    for (int i = w; i < Lp; i += 8) {
        const float e = s[i];
        int cnt = 0;
        for (int j0 = 0; j0 < Lp; j0 += 32) {
            const int j = j0 + l;
            const bool pred = (j < Lp) && ((s[j] > e) || (s[j] == e && j < i));
            cnt += __popc(__ballot_sync(0xffffffffu, pred));
        }
        if (l == 0) {
            outRes[b * Lp + i]  = (float)cnt;
            outMask[b * Lp + i] = (cnt >= LEN_KEEP) ? 1.0f : 0.0f;
            if (cnt < LEN_KEEP) g_keep[b * LEN_KEEP + cnt] = i;
        }
    }
}

// grid (49, 16): each block copies one kept row of 1024 floats via float4.
__global__ void gather_kernel(const float* __restrict__ x, float* __restrict__ out) {
    const int row = blockIdx.x, b = blockIdx.y;
    const int src = g_keep[b * LEN_KEEP + row];
    const float4* xs = (const float4*)(x + ((size_t)b * Lp + src) * Dd);
    float4* od = (float4*)(out + ((size_t)b * LEN_KEEP + row) * Dd);
    od[threadIdx.x] = xs[threadIdx.x];
}

extern "C" void kernel_launch(void* const* d_in, const int* in_sizes, int n_in,
                              void* d_out, int out_size) {
    (void)in_sizes; (void)n_in; (void)out_size;
    const float* x   = (const float*)d_in[0];   // (16,196,1024) fp32
    const float* img = (const float*)d_in[1];   // (16,196,768)  fp32
    float* out = (float*)d_out;                 // [x_masked | mask | ids_restore]

    minmax_kernel<<<MM_BLOCKS, 256>>>(img);
    mm_reduce_kernel<<<1, 256>>>();
    entropy_kernel<<<NPATCH, 256>>>(img);
    rank_kernel<<<NB, 256>>>(out);
    gather_kernel<<<dim3(LEN_KEEP, NB), 256>>>(x, out);
}

// round 17
// speedup vs baseline: 1.0392x; 1.0363x over previous
#include <cuda_runtime.h>

namespace {
constexpr int NB       = 16;
constexpr int Lp       = 196;
constexpr int Dd       = 1024;
constexpr int PPIX     = 768;
constexpr int NBINS    = 64;
constexpr int LEN_KEEP = 49;
constexpr int NPATCH   = NB * Lp;            // 3136
constexpr int TOTAL_PIX = NPATCH * PPIX;
constexpr int MM_BLOCKS = 1184;
}

__device__ uint2  g_mm[MM_BLOCKS];
__device__ float2 g_mmf;
__device__ float  g_ent0[NPATCH];
__device__ int    g_keep[NB * LEN_KEEP];

__device__ __forceinline__ unsigned fenc(float f) {
    unsigned b = __float_as_uint(f);
    return (b & 0x80000000u) ? ~b : (b | 0x80000000u);
}
__device__ __forceinline__ float fdec(unsigned u) {
    return (u & 0x80000000u) ? __uint_as_float(u & 0x7FFFFFFFu)
                             : __uint_as_float(~u);
}

__device__ __forceinline__ float exp_acc(float x) {
#ifndef __FAST_MATH__
    return expf(x);
#else
    float j = __fmaf_rn(x, 1.4426950408889634f, 12582912.0f);
    float n = __fadd_rn(j, -12582912.0f);
    float r = __fmaf_rn(n, -0.693359375f, x);
    r = __fmaf_rn(n, 2.12194440e-4f, r);
    float p = 1.3888889e-3f;
    p = __fmaf_rn(p, r, 8.3333333e-3f);
    p = __fmaf_rn(p, r, 4.1666668e-2f);
    p = __fmaf_rn(p, r, 1.6666667e-1f);
    p = __fmaf_rn(p, r, 0.5f);
    p = __fmaf_rn(p, r, 1.0f);
    p = __fmaf_rn(p, r, 1.0f);
    int ni = (int)n;
    float sc = __int_as_float((ni + 127) << 23);
    return p * sc;
#endif
}
__device__ __forceinline__ float log_acc(float x) {
#ifndef __FAST_MATH__
    return logf(x);
#else
    int ei = (int)(__float_as_uint(x) >> 23) - 127;
    float m = __uint_as_float((__float_as_uint(x) & 0x007FFFFFu) | 0x3F800000u);
    if (m > 1.41421356f) { m *= 0.5f; ei += 1; }
    float f = m - 1.0f;
    float u = f / (2.0f + f);
    float u2 = u * u;
    float pp = 0.0944026f;
    pp = __fmaf_rn(pp, u2, 0.132909f);
    pp = __fmaf_rn(pp, u2, 0.199887f);
    pp = __fmaf_rn(pp, u2, 0.4f);
    pp = __fmaf_rn(pp, u2, 0.666666687f);
    pp = __fmaf_rn(pp, u2, 2.0f);
    float r = pp * u;
    return __fmaf_rn((float)ei, 0.693147182f, r);
#endif
}

__device__ __forceinline__ float bin_value(int b) {
    return (b == NBINS - 1) ? 1.0f : __fmul_rn((float)b, 1.0f / 63.0f);
}

// Correctly-rounded res/0.01f via Markstein refinement (bit-identical to
// __fdiv_rn for all normal res; res is a difference of fp32 in [0,1] so it
// is never denormal). y = RN(1/0.01f) = 100.0f exactly.
__device__ __forceinline__ float div_by_sigma(float res) {
    const float q0 = __fmul_rn(res, 100.0f);
    const float rm = __fmaf_rn(q0, -0.01f, res);
    return __fmaf_rn(rm, 100.0f, q0);
}

__global__ void minmax_kernel(const float* __restrict__ img) {
    __shared__ unsigned smin[8], smax[8];
    unsigned lmin = 0xFFFFFFFFu, lmax = 0u;
    const int n4 = TOTAL_PIX / 4;
    const float4* p4 = (const float4*)img;
    for (int i = blockIdx.x * blockDim.x + threadIdx.x; i < n4;
         i += blockDim.x * gridDim.x) {
        float4 v = p4[i];
        unsigned e;
        e = fenc(v.x); lmin = min(lmin, e); lmax = max(lmax, e);
        e = fenc(v.y); lmin = min(lmin, e); lmax = max(lmax, e);
        e = fenc(v.z); lmin = min(lmin, e); lmax = max(lmax, e);
        e = fenc(v.w); lmin = min(lmin, e); lmax = max(lmax, e);
    }
#pragma unroll
    for (int o = 16; o; o >>= 1) {
        lmin = min(lmin, __shfl_xor_sync(0xffffffffu, lmin, o));
        lmax = max(lmax, __shfl_xor_sync(0xffffffffu, lmax, o));
    }
    const int w = threadIdx.x >> 5;
    if ((threadIdx.x & 31) == 0) { smin[w] = lmin; smax[w] = lmax; }
    __syncthreads();
    if (threadIdx.x == 0) {
        lmin = smin[0]; lmax = smax[0];
#pragma unroll
        for (int j = 1; j < 8; j++) { lmin = min(lmin, smin[j]); lmax = max(lmax, smax[j]); }
        g_mm[blockIdx.x] = make_uint2(lmin, lmax);
    }
}

__global__ void mm_reduce_kernel() {
    __shared__ unsigned smin[8], smax[8];
    const int tid = threadIdx.x;
    unsigned lmin = 0xFFFFFFFFu, lmax = 0u;
    for (int i = tid; i < MM_BLOCKS; i += 256) {
        uint2 v = g_mm[i];
        lmin = min(lmin, v.x); lmax = max(lmax, v.y);
    }
#pragma unroll
    for (int o = 16; o; o >>= 1) {
        lmin = min(lmin, __shfl_xor_sync(0xffffffffu, lmin, o));
        lmax = max(lmax, __shfl_xor_sync(0xffffffffu, lmax, o));
    }
    const int w = tid >> 5;
    if ((tid & 31) == 0) { smin[w] = lmin; smax[w] = lmax; }
    __syncthreads();
    if (tid == 0) {
        lmin = smin[0]; lmax = smax[0];
#pragma unroll
        for (int j = 1; j < 8; j++) { lmin = min(lmin, smin[j]); lmax = max(lmax, smax[j]); }
        g_mmf = make_float2(fdec(lmin), fdec(lmax));
    }
}

// alignment filler so entropy_kernel lands at launch index 3 (the slot the
// ncu capture reports) — removed once profiling is done.
__global__ void nop_kernel() {}

// Hypothesis-0 entropy, bit-exact (chain orders verbatim R16).
__global__ __launch_bounds__(256) void entropy_kernel(const float* __restrict__ img) {
    __shared__ float s_nv[PPIX];
    __shared__ float s_tv[8][PPIX];
    __shared__ float s_pdf[NBINS];
    __shared__ float s_e8[8][8];
    __shared__ float s_tmp[NBINS];

    const int p   = blockIdx.x;
    const int tid = threadIdx.x;
    const int w   = tid >> 5;
    const int l   = tid & 31;
    const int cls = l & 7;

    const float2 mm   = g_mmf;
    const float vmin  = mm.x;
    const float range = __fadd_rn(mm.y, -vmin);

    const float* base = img + (size_t)p * PPIX;
    for (int i = tid; i < PPIX; i += 256)
        s_nv[i] = __fdiv_rn(__fadd_rn(base[i], -vmin), range);
    __syncthreads();

    float* tv = s_tv[w];
    const unsigned ltmask = (1u << l) - 1u;
    const unsigned lbit   = 1u << l;
    const unsigned cm = 0x01010101u << cls;

    for (int bin = w; bin < NBINS; bin += 8) {
        const float binv = bin_value(bin);
        const float fb   = (float)bin;

        // Phase A (chunked): 8 independent ballots, then consume
        int cntc = 0;
#pragma unroll
        for (int kc = 0; kc < 3; kc++) {
            float    nv8[8];
            unsigned bal8[8];
#pragma unroll
            for (int j = 0; j < 8; j++) {
                nv8[j] = s_nv[l + 32 * (kc * 8 + j)];
                const bool iw = fabsf(__fmaf_rn(nv8[j], 63.0f, -fb)) <= 6.0f;
                bal8[j] = __ballot_sync(0xffffffffu, iw);
            }
#pragma unroll
            for (int j = 0; j < 8; j++) {
                const unsigned mc = bal8[j] & cm;
                if (bal8[j] & lbit)
                    tv[(cntc + __popc(mc & ltmask)) * 8 + cls] = nv8[j];
                cntc += __popc(mc);
            }
        }
        __syncwarp();

        // Phase B: dense terms in place (identical term values; Markstein div)
        for (int i = (l >> 3); i < cntc; i += 4) {
            const int s = i * 8 + cls;
            const float nvv = tv[s];
            const float res = __fadd_rn(nvv, -binv);
            const float z   = div_by_sigma(res);
            tv[s] = exp_acc(__fmul_rn(-0.5f, __fmul_rn(z, z)));
        }
        __syncwarp();

        // Phase C: 8 stride-8 chains, in-order (identical fadd sequence)
        if (l < 8) {
            float chain = 0.0f;
            int i = 0;
            for (; i + 6 <= cntc; i += 6) {
                const float a0 = tv[(i + 0) * 8 + l];
                const float a1 = tv[(i + 1) * 8 + l];
                const float a2 = tv[(i + 2) * 8 + l];
                const float a3 = tv[(i + 3) * 8 + l];
                const float a4 = tv[(i + 4) * 8 + l];
                const float a5 = tv[(i + 5) * 8 + l];
                chain = __fadd_rn(chain, a0);
                chain = __fadd_rn(chain, a1);
                chain = __fadd_rn(chain, a2);
                chain = __fadd_rn(chain, a3);
                chain = __fadd_rn(chain, a4);
                chain = __fadd_rn(chain, a5);
            }
            for (; i < cntc; i++)
                chain = __fadd_rn(chain, tv[i * 8 + l]);
            s_e8[w][l] = chain;
        }
        __syncwarp();

        if (l == 0) {
            const float* E8 = s_e8[w];
            float B[4];
#pragma unroll
            for (int j = 0; j < 4; j++) B[j] = __fadd_rn(E8[j], E8[j + 4]);
            const float m0 = __fadd_rn(__fadd_rn(B[0], B[1]), __fadd_rn(B[2], B[3]));
            s_pdf[bin] = __fdiv_rn(m0, 768.0f);
        }
        __syncwarp();
    }
    __syncthreads();

    if (w == 0) {
        if (l < 8) {
            float E = s_pdf[l];
#pragma unroll
            for (int k = 1; k < 8; k++) E = __fadd_rn(E, s_pdf[l + 8 * k]);
            s_e8[0][l] = E;
        }
        __syncwarp();
        float norm;
        if (l == 0) {
            const float* E = s_e8[0];
            float B[4];
#pragma unroll
            for (int j = 0; j < 4; j++) B[j] = __fadd_rn(E[j], E[j + 4]);
            norm = __fadd_rn(__fadd_rn(__fadd_rn(B[0], B[1]),
                                       __fadd_rn(B[2], B[3])), 1e-19f);
        }
        norm = __shfl_sync(0xffffffffu, norm, 0);

        {
            const float pa = __fadd_rn(__fdiv_rn(s_pdf[l], norm), 1e-19f);
            s_tmp[l] = __fmul_rn(pa, log_acc(pa));
            const float pb = __fadd_rn(__fdiv_rn(s_pdf[l + 32], norm), 1e-19f);
            s_tmp[l + 32] = __fmul_rn(pb, log_acc(pb));
        }
        __syncwarp();
        if (l < 8) {
            float E = s_tmp[l];
#pragma unroll
            for (int k = 1; k < 8; k++) E = __fadd_rn(E, s_tmp[l + 8 * k]);
            s_e8[0][l] = E;
        }
        __syncwarp();
        if (l == 0) {
            const float* E = s_e8[0];
            float B[4];
#pragma unroll
            for (int j = 0; j < 4; j++) B[j] = __fadd_rn(E[j], E[j + 4]);
            const float H = __fadd_rn(__fadd_rn(B[0], B[1]), __fadd_rn(B[2], B[3]));
            g_ent0[p] = -H;
        }
    }
}

// ranks: grid (16, 7) — each block covers 28 rows of one batch (same
// predicate / writes as before, 6x fewer serial ballot rounds per warp).
__global__ void rank_kernel(float* __restrict__ out) {
    __shared__ float s[Lp];
    const int b = blockIdx.x, seg = blockIdx.y, tid = threadIdx.x;
    const int w = tid >> 5, l = tid & 31;

    if (tid < Lp) s[tid] = g_ent0[b * Lp + tid];
    __syncthreads();

    float* outMask = out + (size_t)NB * LEN_KEEP * Dd;
    float* outRes  = outMask + (size_t)NB * Lp;

    const int i0 = seg * 28;
    for (int i = i0 + w; i < i0 + 28; i += 8) {
        const float e = s[i];
        int cnt = 0;
        for (int j0 = 0; j0 < Lp; j0 += 32) {
            const int j = j0 + l;
            const bool pred = (j < Lp) && ((s[j] > e) || (s[j] == e && j < i));
            cnt += __popc(__ballot_sync(0xffffffffu, pred));
        }
        if (l == 0) {
            outRes[b * Lp + i]  = (float)cnt;
            outMask[b * Lp + i] = (cnt >= LEN_KEEP) ? 1.0f : 0.0f;
            if (cnt < LEN_KEEP) g_keep[b * LEN_KEEP + cnt] = i;
        }
    }
}

// grid (49, 16): each block copies one kept row of 1024 floats via float4.
__global__ void gather_kernel(const float* __restrict__ x, float* __restrict__ out) {
    const int row = blockIdx.x, b = blockIdx.y;
    const int src = g_keep[b * LEN_KEEP + row];
    const float4* xs = (const float4*)(x + ((size_t)b * Lp + src) * Dd);
    float4* od = (float4*)(out + ((size_t)b * LEN_KEEP + row) * Dd);
    od[threadIdx.x] = xs[threadIdx.x];
}

extern "C" void kernel_launch(void* const* d_in, const int* in_sizes, int n_in,
                              void* d_out, int out_size) {
    (void)in_sizes; (void)n_in; (void)out_size;
    const float* x   = (const float*)d_in[0];
    const float* img = (const float*)d_in[1];
    float* out = (float*)d_out;

    minmax_kernel<<<MM_BLOCKS, 256>>>(img);      // launch 0
    mm_reduce_kernel<<<1, 256>>>();              // launch 1
    nop_kernel<<<1, 32>>>();                     // launch 2 (alignment)
    entropy_kernel<<<NPATCH, 256>>>(img);        // launch 3 <- ncu capture slot
    rank_kernel<<<dim3(NB, 7), 256>>>(out);      // launch 4
    gather_kernel<<<dim3(LEN_KEEP, NB), 256>>>(x, out);  // launch 5
}